// round 1
// baseline (speedup 1.0000x reference)
#include <cuda_runtime.h>
#include <math.h>

#define TTOK 4096
#define HDIM 2048
#define NEXP 64
#define TOPK 8
#define IDIM 768
#define NPAIR (TTOK * TOPK)   /* 32768 */
#define CAP   TTOK            /* worst-case rows per expert */

/* ---------------- scratch (static device globals: alloc-free) -------------- */
__device__ float g_logits[TTOK * NEXP];            /* 1 MB   */
__device__ float g_topkw[NPAIR];                   /* 128 KB */
__device__ int   g_counts[NEXP];
__device__ int   g_offsets[NEXP];
__device__ int   g_bucket[NEXP * CAP];             /* pair ids grouped by expert */
__device__ float g_act[(size_t)NPAIR * IDIM];      /* 96 MB  */
__device__ float g_pairout[(size_t)NPAIR * HDIM];  /* 256 MB */

#define LD4(p) (*reinterpret_cast<const float4*>(p))

/* ---------------- stage 0: zero expert counters ---------------------------- */
__global__ void k_zero_counts() {
    if (threadIdx.x < NEXP) g_counts[threadIdx.x] = 0;
}

/* ---------------- stage 1: router GEMM  logits[T,64] = x @ gw^T ------------ */
/* tile 64x64, K-tile 16, 256 threads, 4x4 microtile */
__global__ void __launch_bounds__(256) k_router(const float* __restrict__ x,
                                                const float* __restrict__ gw) {
    __shared__ float As[16][64];
    __shared__ float Bs[16][64];
    const int t  = threadIdx.x;
    const int m0 = blockIdx.x * 64;
    const int tx = t & 15, ty = t >> 4;
    const int mload = t >> 2;       /* 0..63: row for A, col (expert) for B */
    const int kq    = (t & 3) * 4;  /* float4 offset in k */
    float acc[4][4] = {};

    for (int k0 = 0; k0 < HDIM; k0 += 16) {
        float4 av = LD4(x  + (size_t)(m0 + mload) * HDIM + k0 + kq);
        float4 bv = LD4(gw + (size_t)mload        * HDIM + k0 + kq);
        __syncthreads();
        As[kq + 0][mload] = av.x; As[kq + 1][mload] = av.y;
        As[kq + 2][mload] = av.z; As[kq + 3][mload] = av.w;
        Bs[kq + 0][mload] = bv.x; Bs[kq + 1][mload] = bv.y;
        Bs[kq + 2][mload] = bv.z; Bs[kq + 3][mload] = bv.w;
        __syncthreads();
#pragma unroll
        for (int k = 0; k < 16; k++) {
            float4 a = LD4(&As[k][ty * 4]);
            float4 b = LD4(&Bs[k][tx * 4]);
            float ax[4] = {a.x, a.y, a.z, a.w};
            float bx[4] = {b.x, b.y, b.z, b.w};
#pragma unroll
            for (int i = 0; i < 4; i++)
#pragma unroll
                for (int j = 0; j < 4; j++)
                    acc[i][j] = fmaf(ax[i], bx[j], acc[i][j]);
        }
    }
#pragma unroll
    for (int i = 0; i < 4; i++)
#pragma unroll
        for (int j = 0; j < 4; j++)
            g_logits[(size_t)(m0 + ty * 4 + i) * NEXP + tx * 4 + j] = acc[i][j];
}

/* ---------------- stage 2: top-8 + renormalized softmax + bucketize -------- */
/* renormalized top-k softmax == softmax over the top-k logits (Z cancels)    */
__global__ void k_topk() {
    int t = blockIdx.x * blockDim.x + threadIdx.x;
    if (t >= TTOK) return;
    float l[NEXP];
    for (int e = 0; e < NEXP; e++) l[e] = g_logits[(size_t)t * NEXP + e];
    float vals[TOPK]; int ids[TOPK];
    for (int k = 0; k < TOPK; k++) {
        float best = -3.4e38f; int bi = 0;
        for (int e = 0; e < NEXP; e++)
            if (l[e] > best) { best = l[e]; bi = e; }
        vals[k] = best; ids[k] = bi; l[bi] = -3.4e38f;
    }
    float m = vals[0], s = 0.f, wv[TOPK];
    for (int k = 0; k < TOPK; k++) { wv[k] = expf(vals[k] - m); s += wv[k]; }
    float inv = 1.f / s;
    for (int k = 0; k < TOPK; k++) {
        g_topkw[t * TOPK + k] = wv[k] * inv;
        int e   = ids[k];
        int pos = atomicAdd(&g_counts[e], 1);
        g_bucket[e * CAP + pos] = t * TOPK + k;   /* pair id */
    }
}

/* ---------------- stage 3: exclusive scan of counts ------------------------ */
__global__ void k_scan() {
    int s = 0;
    for (int e = 0; e < NEXP; e++) { g_offsets[e] = s; s += g_counts[e]; }
}

/* ---------------- stage 4: fused gate/up grouped GEMM + SiLU --------------- */
/* per block: 128(M) x 64(N) tile of BOTH gate and up for expert e;
   A rows gathered from x via bucket; epilogue act = silu(g)*u -> g_act       */
__global__ void __launch_bounds__(256) k_gemm1(const float* __restrict__ x,
                                               const float* __restrict__ wgt,
                                               const float* __restrict__ wup) {
    const int e    = blockIdx.z;
    const int rows = g_counts[e];
    const int m0   = blockIdx.y * 128;
    if (m0 >= rows) return;
    const int n0 = blockIdx.x * 64;

    __shared__ float As[16][128];
    __shared__ float Bgs[16][64];
    __shared__ float Bus[16][64];
    __shared__ int   toks[128];

    const int t = threadIdx.x;
    if (t < 128) {
        int r = m0 + t;
        toks[t] = (r < rows) ? (g_bucket[e * CAP + r] >> 3) : -1;
    }
    __syncthreads();

    const float* bg = wgt + (size_t)e * HDIM * IDIM;
    const float* bu = wup + (size_t)e * HDIM * IDIM;

    const int tx = t & 15, ty = t >> 4;       /* micro 8m x 4n */
    const int arow = t >> 1;                  /* 0..127 */
    const int ak   = (t & 1) * 8;             /* k base: 0 or 8 */
    const int bk   = t >> 4;                  /* 0..15 */
    const int bn   = (t & 15) * 4;

    const int  tok0 = toks[arow];
    const bool aval = (tok0 >= 0);
    const float* aptr = aval ? (x + (size_t)tok0 * HDIM) : x;

    float4 pa0, pa1, pbg, pbu;
    const float4 fz = make_float4(0.f, 0.f, 0.f, 0.f);
    /* prefetch k-tile 0 */
    if (aval) { pa0 = LD4(aptr + ak); pa1 = LD4(aptr + ak + 4); }
    else      { pa0 = fz; pa1 = fz; }
    pbg = LD4(bg + (size_t)bk * IDIM + n0 + bn);
    pbu = LD4(bu + (size_t)bk * IDIM + n0 + bn);

    float accg[8][4] = {}, accu[8][4] = {};
    const int KT = HDIM / 16;
    for (int kt = 0; kt < KT; ++kt) {
        __syncthreads();
        As[ak + 0][arow] = pa0.x; As[ak + 1][arow] = pa0.y;
        As[ak + 2][arow] = pa0.z; As[ak + 3][arow] = pa0.w;
        As[ak + 4][arow] = pa1.x; As[ak + 5][arow] = pa1.y;
        As[ak + 6][arow] = pa1.z; As[ak + 7][arow] = pa1.w;
        *reinterpret_cast<float4*>(&Bgs[bk][bn]) = pbg;
        *reinterpret_cast<float4*>(&Bus[bk][bn]) = pbu;
        __syncthreads();
        if (kt + 1 < KT) {                     /* prefetch next tile */
            int k0 = (kt + 1) * 16;
            if (aval) { pa0 = LD4(aptr + k0 + ak); pa1 = LD4(aptr + k0 + ak + 4); }
            pbg = LD4(bg + (size_t)(k0 + bk) * IDIM + n0 + bn);
            pbu = LD4(bu + (size_t)(k0 + bk) * IDIM + n0 + bn);
        }
#pragma unroll
        for (int k = 0; k < 16; k++) {
            float4 a0 = LD4(&As[k][ty * 8]);
            float4 a1 = LD4(&As[k][ty * 8 + 4]);
            float4 g4 = LD4(&Bgs[k][tx * 4]);
            float4 u4 = LD4(&Bus[k][tx * 4]);
            float ax[8] = {a0.x, a0.y, a0.z, a0.w, a1.x, a1.y, a1.z, a1.w};
            float gx[4] = {g4.x, g4.y, g4.z, g4.w};
            float ux[4] = {u4.x, u4.y, u4.z, u4.w};
#pragma unroll
            for (int i = 0; i < 8; i++)
#pragma unroll
                for (int j = 0; j < 4; j++) {
                    accg[i][j] = fmaf(ax[i], gx[j], accg[i][j]);
                    accu[i][j] = fmaf(ax[i], ux[j], accu[i][j]);
                }
        }
    }
    const int off = g_offsets[e];
#pragma unroll
    for (int i = 0; i < 8; i++) {
        int r = m0 + ty * 8 + i;
        if (r < rows) {
            float4 o;
            float g0 = accg[i][0], g1 = accg[i][1], g2 = accg[i][2], g3 = accg[i][3];
            o.x = g0 / (1.f + expf(-g0)) * accu[i][0];
            o.y = g1 / (1.f + expf(-g1)) * accu[i][1];
            o.z = g2 / (1.f + expf(-g2)) * accu[i][2];
            o.w = g3 / (1.f + expf(-g3)) * accu[i][3];
            *reinterpret_cast<float4*>(&g_act[(size_t)(off + r) * IDIM + n0 + tx * 4]) = o;
        }
    }
}

/* ---------------- stage 5: down-proj grouped GEMM -------------------------- */
__global__ void __launch_bounds__(256) k_gemm2(const float* __restrict__ wdn) {
    const int e    = blockIdx.z;
    const int rows = g_counts[e];
    const int m0   = blockIdx.y * 128;
    if (m0 >= rows) return;
    const int n0  = blockIdx.x * 64;
    const int off = g_offsets[e];

    __shared__ float As[16][128];
    __shared__ float Bs[16][64];
    __shared__ int   prs[128];

    const int t = threadIdx.x;
    if (t < 128) {
        int r = m0 + t;
        prs[t] = (r < rows) ? g_bucket[e * CAP + r] : -1;
    }
    __syncthreads();

    const float* b = wdn + (size_t)e * IDIM * HDIM;
    const int tx = t & 15, ty = t >> 4;
    const int arow = t >> 1;
    const int ak   = (t & 1) * 8;
    const int bk   = t >> 4;
    const int bn   = (t & 15) * 4;

    const bool aval = (m0 + arow < rows);
    const float* aptr = g_act + (size_t)(off + m0 + arow) * IDIM;

    float4 pa0, pa1, pb;
    const float4 fz = make_float4(0.f, 0.f, 0.f, 0.f);
    if (aval) { pa0 = LD4(aptr + ak); pa1 = LD4(aptr + ak + 4); }
    else      { pa0 = fz; pa1 = fz; }
    pb = LD4(b + (size_t)bk * HDIM + n0 + bn);

    float acc[8][4] = {};
    const int KT = IDIM / 16;
    for (int kt = 0; kt < KT; ++kt) {
        __syncthreads();
        As[ak + 0][arow] = pa0.x; As[ak + 1][arow] = pa0.y;
        As[ak + 2][arow] = pa0.z; As[ak + 3][arow] = pa0.w;
        As[ak + 4][arow] = pa1.x; As[ak + 5][arow] = pa1.y;
        As[ak + 6][arow] = pa1.z; As[ak + 7][arow] = pa1.w;
        *reinterpret_cast<float4*>(&Bs[bk][bn]) = pb;
        __syncthreads();
        if (kt + 1 < KT) {
            int k0 = (kt + 1) * 16;
            if (aval) { pa0 = LD4(aptr + k0 + ak); pa1 = LD4(aptr + k0 + ak + 4); }
            pb = LD4(b + (size_t)(k0 + bk) * HDIM + n0 + bn);
        }
#pragma unroll
        for (int k = 0; k < 16; k++) {
            float4 a0 = LD4(&As[k][ty * 8]);
            float4 a1 = LD4(&As[k][ty * 8 + 4]);
            float4 b4 = LD4(&Bs[k][tx * 4]);
            float ax[8] = {a0.x, a0.y, a0.z, a0.w, a1.x, a1.y, a1.z, a1.w};
            float bx[4] = {b4.x, b4.y, b4.z, b4.w};
#pragma unroll
            for (int i = 0; i < 8; i++)
#pragma unroll
                for (int j = 0; j < 4; j++)
                    acc[i][j] = fmaf(ax[i], bx[j], acc[i][j]);
        }
    }
#pragma unroll
    for (int i = 0; i < 8; i++) {
        int r = ty * 8 + i;
        int p = prs[r];
        if (p >= 0) {
            float4 o = {acc[i][0], acc[i][1], acc[i][2], acc[i][3]};
            *reinterpret_cast<float4*>(&g_pairout[(size_t)p * HDIM + n0 + tx * 4]) = o;
        }
    }
}

/* ---------------- stage 6: weighted combine over K experts ----------------- */
__global__ void k_combine(float* __restrict__ out) {
    const int tok = blockIdx.x;
    float w[TOPK];
#pragma unroll
    for (int k = 0; k < TOPK; k++) w[k] = g_topkw[tok * TOPK + k];
    for (int h4 = threadIdx.x; h4 < HDIM / 4; h4 += blockDim.x) {
        float4 s = make_float4(0.f, 0.f, 0.f, 0.f);
#pragma unroll
        for (int k = 0; k < TOPK; k++) {
            float4 v = LD4(&g_pairout[(size_t)(tok * TOPK + k) * HDIM + h4 * 4]);
            s.x = fmaf(w[k], v.x, s.x); s.y = fmaf(w[k], v.y, s.y);
            s.z = fmaf(w[k], v.z, s.z); s.w = fmaf(w[k], v.w, s.w);
        }
        *reinterpret_cast<float4*>(&out[(size_t)tok * HDIM + h4 * 4]) = s;
    }
}

/* ---------------- launch ---------------------------------------------------- */
extern "C" void kernel_launch(void* const* d_in, const int* /*in_sizes*/, int /*n_in*/,
                              void* d_out, int /*out_size*/) {
    const float* x   = (const float*)d_in[0];  /* hidden_states [2,2048,2048] */
    const float* gw  = (const float*)d_in[1];  /* gate_weight   [64,2048]     */
    const float* wgt = (const float*)d_in[2];  /* w_gate  [64,2048,768]       */
    const float* wup = (const float*)d_in[3];  /* w_up    [64,2048,768]       */
    const float* wdn = (const float*)d_in[4];  /* w_down  [64,768,2048]       */
    float* out = (float*)d_out;

    k_zero_counts<<<1, 64>>>();
    k_router<<<TTOK / 64, 256>>>(x, gw);
    k_topk<<<TTOK / 256, 256>>>();
    k_scan<<<1, 1>>>();
    k_gemm1<<<dim3(IDIM / 64, CAP / 128, NEXP), 256>>>(x, wgt, wup);
    k_gemm2<<<dim3(HDIM / 64, CAP / 128, NEXP), 256>>>(wdn);
    k_combine<<<TTOK, 256>>>(out);
}

// round 3
// speedup vs baseline: 1.9438x; 1.9438x over previous
#include <cuda_runtime.h>
#include <math.h>
#include <stdint.h>

#define TTOK 4096
#define HDIM 2048
#define NEXP 64
#define TOPK 8
#define IDIM 768
#define NPAIR (TTOK * TOPK)
#define CAP   TTOK

/* ---------------- scratch ---------------- */
__device__ float g_logits[TTOK * NEXP];
__device__ float g_topkw[NPAIR];
__device__ int   g_counts[NEXP];
__device__ int   g_offsets[NEXP];
__device__ int   g_bucket[NEXP * CAP];
__device__ float g_act[(size_t)NPAIR * IDIM];
__device__ float g_pairout[(size_t)NPAIR * HDIM];

#define LD4(p) (*reinterpret_cast<const float4*>(p))

/* ---------------- helpers ---------------- */
__device__ __forceinline__ uint32_t f2tf32(float f) {
    uint32_t r; asm("cvt.rna.tf32.f32 %0, %1;" : "=r"(r) : "f"(f)); return r;
}
__device__ __forceinline__ void mma8(float* d, const uint32_t* a, const uint32_t* b) {
    asm volatile(
        "mma.sync.aligned.m16n8k8.row.col.f32.tf32.tf32.f32 "
        "{%0,%1,%2,%3}, {%4,%5,%6,%7}, {%8,%9}, {%0,%1,%2,%3};"
        : "+f"(d[0]), "+f"(d[1]), "+f"(d[2]), "+f"(d[3])
        : "r"(a[0]), "r"(a[1]), "r"(a[2]), "r"(a[3]), "r"(b[0]), "r"(b[1]));
}
/* store float4 as 4 tf32 words (16B-aligned dst) */
__device__ __forceinline__ void sts4tf(uint32_t* p, float4 v) {
    uint4 u; u.x = f2tf32(v.x); u.y = f2tf32(v.y); u.z = f2tf32(v.z); u.w = f2tf32(v.w);
    *reinterpret_cast<uint4*>(p) = u;
}

/* A tile: [128][20] words (pad 20 -> conflict-free frag loads)
   B tile: [16][136] words (pad 136 -> conflict-free frag loads)  */
#define A_LDA 20
#define B_LDB 136
#define A_WORDS (128 * A_LDA)            /* 2560 */
#define B_WORDS (16 * B_LDB)             /* 2176 */

/* ---------------- router path ---------------- */
__global__ void k_zero_counts() { if (threadIdx.x < NEXP) g_counts[threadIdx.x] = 0; }

__global__ void __launch_bounds__(256) k_router(const float* __restrict__ x,
                                                const float* __restrict__ gw) {
    __shared__ float As[16][64];
    __shared__ float Bs[16][64];
    const int t = threadIdx.x;
    const int m0 = blockIdx.x * 64;
    const int tx = t & 15, ty = t >> 4;
    const int mload = t >> 2;
    const int kq = (t & 3) * 4;
    float acc[4][4] = {};
    for (int k0 = 0; k0 < HDIM; k0 += 16) {
        float4 av = LD4(x + (size_t)(m0 + mload) * HDIM + k0 + kq);
        float4 bv = LD4(gw + (size_t)mload * HDIM + k0 + kq);
        __syncthreads();
        As[kq + 0][mload] = av.x; As[kq + 1][mload] = av.y;
        As[kq + 2][mload] = av.z; As[kq + 3][mload] = av.w;
        Bs[kq + 0][mload] = bv.x; Bs[kq + 1][mload] = bv.y;
        Bs[kq + 2][mload] = bv.z; Bs[kq + 3][mload] = bv.w;
        __syncthreads();
#pragma unroll
        for (int k = 0; k < 16; k++) {
            float4 a = LD4(&As[k][ty * 4]);
            float4 b = LD4(&Bs[k][tx * 4]);
            float ax[4] = {a.x, a.y, a.z, a.w};
            float bx[4] = {b.x, b.y, b.z, b.w};
#pragma unroll
            for (int i = 0; i < 4; i++)
#pragma unroll
                for (int j = 0; j < 4; j++)
                    acc[i][j] = fmaf(ax[i], bx[j], acc[i][j]);
        }
    }
#pragma unroll
    for (int i = 0; i < 4; i++)
#pragma unroll
        for (int j = 0; j < 4; j++)
            g_logits[(size_t)(m0 + ty * 4 + i) * NEXP + tx * 4 + j] = acc[i][j];
}

__global__ void k_topk() {
    int t = blockIdx.x * blockDim.x + threadIdx.x;
    if (t >= TTOK) return;
    float l[NEXP];
    for (int e = 0; e < NEXP; e++) l[e] = g_logits[(size_t)t * NEXP + e];
    float vals[TOPK]; int ids[TOPK];
    for (int k = 0; k < TOPK; k++) {
        float best = -3.4e38f; int bi = 0;
        for (int e = 0; e < NEXP; e++)
            if (l[e] > best) { best = l[e]; bi = e; }
        vals[k] = best; ids[k] = bi; l[bi] = -3.4e38f;
    }
    float m = vals[0], s = 0.f, wv[TOPK];
    for (int k = 0; k < TOPK; k++) { wv[k] = expf(vals[k] - m); s += wv[k]; }
    float inv = 1.f / s;
    for (int k = 0; k < TOPK; k++) {
        g_topkw[t * TOPK + k] = wv[k] * inv;
        int e = ids[k];
        int pos = atomicAdd(&g_counts[e], 1);
        g_bucket[e * CAP + pos] = t * TOPK + k;
    }
}

__global__ void k_scan() {
    int s = 0;
    for (int e = 0; e < NEXP; e++) { g_offsets[e] = s; s += g_counts[e]; }
}

/* ================= stage 4: fused gate/up tensor-core GEMM + SiLU =================
   CTA 128(M) x 128(N) computing BOTH gate and up. 8 warps, warp tile 64x32.
   smem stage: A[128][20] + Bg[16][136] + Bu[16][136]; double buffered. */
#define G1_STAGE (A_WORDS + 2 * B_WORDS)             /* 6912 words */
#define G1_SMEM  ((128 + 2 * G1_STAGE) * 4)          /* bytes */
__global__ void __launch_bounds__(256)
k_gemm1(const float* __restrict__ x, const float* __restrict__ wgt, const float* __restrict__ wup) {
    extern __shared__ uint32_t sm[];
    const int e = blockIdx.z;
    const int rows = g_counts[e];
    const int m0 = blockIdx.y * 128;
    if (m0 >= rows) return;
    const int n0 = blockIdx.x * 128;
    const int t = threadIdx.x, w = t >> 5, lane = t & 31;
    const int gid = lane >> 2, tig = lane & 3;
    const int wm = w >> 2, wn = w & 3;

    int* toks = (int*)sm;
    if (t < 128) {
        int r = m0 + t;
        toks[t] = (r < rows) ? (g_bucket[e * CAP + r] >> 3) : -1;
    }
    __syncthreads();
    uint32_t* buf = sm + 128;

    const float* bg = wgt + (size_t)e * HDIM * IDIM;
    const float* bu = wup + (size_t)e * HDIM * IDIM;

    /* fill roles: A: thread t -> row t>>1, k-half (t&1)*8.
       B: threads 0-127 gate, 128-255 up; q: k-row q>>3, n-quad (q&7)*16 */
    const int am = t >> 1, akh = (t & 1) * 8;
    const int tokA = toks[am];
    const bool aval = (tokA >= 0);
    const float* aptr = x + (size_t)(aval ? tokA : 0) * HDIM;
    const int bq = t & 127, bk = bq >> 3, bn = (bq & 7) * 16;
    const float* bsrc = (t < 128) ? bg : bu;
    const int boff = (t < 128) ? A_WORDS : (A_WORDS + B_WORDS);

    float4 pa0, pa1, pb0, pb1, pb2, pb3;
    if (aval) { pa0 = LD4(aptr + akh); pa1 = LD4(aptr + akh + 4); }
    else { pa0 = make_float4(0, 0, 0, 0); pa1 = pa0; }
    { const float* s = bsrc + (size_t)bk * IDIM + n0 + bn;
      pb0 = LD4(s); pb1 = LD4(s + 4); pb2 = LD4(s + 8); pb3 = LD4(s + 12); }

    float cg[4][4][4] = {}, cu[4][4][4] = {};

    const int KT = HDIM / 16;
    for (int kt = 0; kt < KT; kt++) {
        uint32_t* st = buf + (kt & 1) * G1_STAGE;
        __syncthreads();
        sts4tf(st + am * A_LDA + akh, pa0);
        sts4tf(st + am * A_LDA + akh + 4, pa1);
        { uint32_t* p = st + boff + bk * B_LDB + bn;
          sts4tf(p, pb0); sts4tf(p + 4, pb1); sts4tf(p + 8, pb2); sts4tf(p + 12, pb3); }
        __syncthreads();
        if (kt + 1 < KT) {
            const int kb = (kt + 1) * 16;
            if (aval) { pa0 = LD4(aptr + kb + akh); pa1 = LD4(aptr + kb + akh + 4); }
            const float* s = bsrc + (size_t)(kb + bk) * IDIM + n0 + bn;
            pb0 = LD4(s); pb1 = LD4(s + 4); pb2 = LD4(s + 8); pb3 = LD4(s + 12);
        }
        const uint32_t* sA  = st;
        const uint32_t* sBg = st + A_WORDS;
        const uint32_t* sBu = st + A_WORDS + B_WORDS;
#pragma unroll
        for (int ks = 0; ks < 2; ks++) {
            uint32_t af[4][4];
#pragma unroll
            for (int mt = 0; mt < 4; mt++) {
                const uint32_t* a = sA + (wm * 64 + mt * 16 + gid) * A_LDA + ks * 8 + tig;
                af[mt][0] = a[0];
                af[mt][1] = a[8 * A_LDA];
                af[mt][2] = a[4];
                af[mt][3] = a[8 * A_LDA + 4];
            }
#pragma unroll
            for (int nt = 0; nt < 4; nt++) {
                const int c = wn * 32 + nt * 8 + gid;
                uint32_t b[2];
                const uint32_t* bp = sBg + (ks * 8 + tig) * B_LDB + c;
                b[0] = bp[0]; b[1] = bp[4 * B_LDB];
#pragma unroll
                for (int mt = 0; mt < 4; mt++) mma8(cg[mt][nt], af[mt], b);
                bp = sBu + (ks * 8 + tig) * B_LDB + c;
                b[0] = bp[0]; b[1] = bp[4 * B_LDB];
#pragma unroll
                for (int mt = 0; mt < 4; mt++) mma8(cu[mt][nt], af[mt], b);
            }
        }
    }
    /* fused SiLU epilogue straight from accumulators */
    const int off = g_offsets[e];
#pragma unroll
    for (int mt = 0; mt < 4; mt++) {
#pragma unroll
        for (int h = 0; h < 2; h++) {
            const int row = m0 + wm * 64 + mt * 16 + gid + h * 8;
            if (row < rows) {
                float* dst = g_act + (size_t)(off + row) * IDIM + n0 + wn * 32;
#pragma unroll
                for (int nt = 0; nt < 4; nt++) {
                    float g0 = cg[mt][nt][h * 2 + 0], g1 = cg[mt][nt][h * 2 + 1];
                    float u0 = cu[mt][nt][h * 2 + 0], u1 = cu[mt][nt][h * 2 + 1];
                    float2 o;
                    o.x = g0 / (1.f + expf(-g0)) * u0;
                    o.y = g1 / (1.f + expf(-g1)) * u1;
                    *reinterpret_cast<float2*>(dst + nt * 8 + 2 * tig) = o;
                }
            }
        }
    }
}

/* ================= stage 5: down-proj tensor-core GEMM ================= */
#define G2_STAGE (A_WORDS + B_WORDS)                 /* 4736 words */
#define G2_SMEM  ((128 + 2 * G2_STAGE) * 4)
__global__ void __launch_bounds__(256)
k_gemm2(const float* __restrict__ wdn) {
    extern __shared__ uint32_t sm[];
    const int e = blockIdx.z;
    const int rows = g_counts[e];
    const int m0 = blockIdx.y * 128;
    if (m0 >= rows) return;
    const int n0 = blockIdx.x * 128;
    const int t = threadIdx.x, w = t >> 5, lane = t & 31;
    const int gid = lane >> 2, tig = lane & 3;
    const int wm = w >> 2, wn = w & 3;
    const int off = g_offsets[e];

    int* prs = (int*)sm;
    if (t < 128) {
        int r = m0 + t;
        prs[t] = (r < rows) ? g_bucket[e * CAP + r] : -1;
    }
    __syncthreads();
    uint32_t* buf = sm + 128;

    const float* bsrc = wdn + (size_t)e * IDIM * HDIM;

    const int am = t >> 1, akh = (t & 1) * 8;
    const bool aval = (m0 + am < rows);
    const float* aptr = g_act + (size_t)(off + m0 + (aval ? am : 0)) * IDIM;
    const int bk = t >> 4, bn = (t & 15) * 8;   /* 256 thr: 16 k-rows x 128 n, 8 floats each */

    float4 pa0, pa1, pb0, pb1;
    if (aval) { pa0 = LD4(aptr + akh); pa1 = LD4(aptr + akh + 4); }
    else { pa0 = make_float4(0, 0, 0, 0); pa1 = pa0; }
    { const float* s = bsrc + (size_t)bk * HDIM + n0 + bn;
      pb0 = LD4(s); pb1 = LD4(s + 4); }

    float cd[4][4][4] = {};

    const int KT = IDIM / 16;
    for (int kt = 0; kt < KT; kt++) {
        uint32_t* st = buf + (kt & 1) * G2_STAGE;
        __syncthreads();
        sts4tf(st + am * A_LDA + akh, pa0);
        sts4tf(st + am * A_LDA + akh + 4, pa1);
        { uint32_t* p = st + A_WORDS + bk * B_LDB + bn;
          sts4tf(p, pb0); sts4tf(p + 4, pb1); }
        __syncthreads();
        if (kt + 1 < KT) {
            const int kb = (kt + 1) * 16;
            if (aval) { pa0 = LD4(aptr + kb + akh); pa1 = LD4(aptr + kb + akh + 4); }
            const float* s = bsrc + (size_t)(kb + bk) * HDIM + n0 + bn;
            pb0 = LD4(s); pb1 = LD4(s + 4);
        }
        const uint32_t* sA = st;
        const uint32_t* sB = st + A_WORDS;
#pragma unroll
        for (int ks = 0; ks < 2; ks++) {
            uint32_t af[4][4];
#pragma unroll
            for (int mt = 0; mt < 4; mt++) {
                const uint32_t* a = sA + (wm * 64 + mt * 16 + gid) * A_LDA + ks * 8 + tig;
                af[mt][0] = a[0];
                af[mt][1] = a[8 * A_LDA];
                af[mt][2] = a[4];
                af[mt][3] = a[8 * A_LDA + 4];
            }
#pragma unroll
            for (int nt = 0; nt < 4; nt++) {
                const int c = wn * 32 + nt * 8 + gid;
                uint32_t b[2];
                const uint32_t* bp = sB + (ks * 8 + tig) * B_LDB + c;
                b[0] = bp[0]; b[1] = bp[4 * B_LDB];
#pragma unroll
                for (int mt = 0; mt < 4; mt++) mma8(cd[mt][nt], af[mt], b);
            }
        }
    }
#pragma unroll
    for (int mt = 0; mt < 4; mt++) {
#pragma unroll
        for (int h = 0; h < 2; h++) {
            const int lr = wm * 64 + mt * 16 + gid + h * 8;
            const int p = prs[lr];
            if (p >= 0) {
                float* dst = g_pairout + (size_t)p * HDIM + n0 + wn * 32;
#pragma unroll
                for (int nt = 0; nt < 4; nt++) {
                    float2 o;
                    o.x = cd[mt][nt][h * 2 + 0];
                    o.y = cd[mt][nt][h * 2 + 1];
                    *reinterpret_cast<float2*>(dst + nt * 8 + 2 * tig) = o;
                }
            }
        }
    }
}

/* ---------------- stage 6: weighted combine ---------------- */
__global__ void k_combine(float* __restrict__ out) {
    const int tok = blockIdx.x;
    float w[TOPK];
#pragma unroll
    for (int k = 0; k < TOPK; k++) w[k] = g_topkw[tok * TOPK + k];
    for (int h4 = threadIdx.x; h4 < HDIM / 4; h4 += blockDim.x) {
        float4 s = make_float4(0.f, 0.f, 0.f, 0.f);
#pragma unroll
        for (int k = 0; k < TOPK; k++) {
            float4 v = LD4(&g_pairout[(size_t)(tok * TOPK + k) * HDIM + h4 * 4]);
            s.x = fmaf(w[k], v.x, s.x); s.y = fmaf(w[k], v.y, s.y);
            s.z = fmaf(w[k], v.z, s.z); s.w = fmaf(w[k], v.w, s.w);
        }
        *reinterpret_cast<float4*>(&out[(size_t)tok * HDIM + h4 * 4]) = s;
    }
}

/* ---------------- launch ---------------- */
extern "C" void kernel_launch(void* const* d_in, const int* /*in_sizes*/, int /*n_in*/,
                              void* d_out, int /*out_size*/) {
    const float* x   = (const float*)d_in[0];
    const float* gw  = (const float*)d_in[1];
    const float* wgt = (const float*)d_in[2];
    const float* wup = (const float*)d_in[3];
    const float* wdn = (const float*)d_in[4];
    float* out = (float*)d_out;

    cudaFuncSetAttribute(k_gemm1, cudaFuncAttributeMaxDynamicSharedMemorySize, G1_SMEM);
    cudaFuncSetAttribute(k_gemm2, cudaFuncAttributeMaxDynamicSharedMemorySize, G2_SMEM);

    k_zero_counts<<<1, 64>>>();
    k_router<<<TTOK / 64, 256>>>(x, gw);
    k_topk<<<TTOK / 256, 256>>>();
    k_scan<<<1, 1>>>();
    k_gemm1<<<dim3(IDIM / 128, CAP / 128, NEXP), 256, G1_SMEM>>>(x, wgt, wup);
    k_gemm2<<<dim3(HDIM / 128, CAP / 128, NEXP), 256, G2_SMEM>>>(wdn);
    k_combine<<<TTOK, 256>>>(out);
}

// round 4
// speedup vs baseline: 3.1827x; 1.6374x over previous
#include <cuda_runtime.h>
#include <cuda_fp16.h>
#include <math.h>
#include <stdint.h>

#define TTOK 4096
#define HDIM 2048
#define NEXP 64
#define TOPK 8
#define IDIM 768
#define NPAIR (TTOK * TOPK)
#define CAP   TTOK

/* ---------------- scratch ---------------- */
__device__ float g_logits[TTOK * NEXP];
__device__ float g_topkw[NPAIR];
__device__ int   g_counts[NEXP];
__device__ int   g_offsets[NEXP];
__device__ int   g_bucket[NEXP * CAP];
/* activations stored fp16; uint4 type forces 16B alignment */
__device__ uint4 g_act4[(size_t)NPAIR * IDIM / 8];

#define LD4(p) (*reinterpret_cast<const float4*>(p))

/* ---------------- helpers ---------------- */
__device__ __forceinline__ uint32_t smem_u32(const void* p) {
    uint32_t a;
    asm("{ .reg .u64 t; cvta.to.shared.u64 t, %1; cvt.u32.u64 %0, t; }" : "=r"(a) : "l"(p));
    return a;
}
__device__ __forceinline__ uint32_t pk2(float x, float y) {
    __half2 h = __floats2half2_rn(x, y);
    return *reinterpret_cast<uint32_t*>(&h);
}
__device__ __forceinline__ uint4 pack8(float4 a, float4 b) {
    return make_uint4(pk2(a.x, a.y), pk2(a.z, a.w), pk2(b.x, b.y), pk2(b.z, b.w));
}
__device__ __forceinline__ void ldsm4(uint32_t* r, uint32_t addr) {
    asm volatile("ldmatrix.sync.aligned.m8n8.x4.shared.b16 {%0,%1,%2,%3}, [%4];"
                 : "=r"(r[0]), "=r"(r[1]), "=r"(r[2]), "=r"(r[3]) : "r"(addr));
}
__device__ __forceinline__ void ldsm2t(uint32_t* r, uint32_t addr) {
    asm volatile("ldmatrix.sync.aligned.m8n8.x2.trans.shared.b16 {%0,%1}, [%2];"
                 : "=r"(r[0]), "=r"(r[1]) : "r"(addr));
}
__device__ __forceinline__ void mma16(float* d, const uint32_t* a, const uint32_t* b) {
    asm volatile(
        "mma.sync.aligned.m16n8k16.row.col.f32.f16.f16.f32 "
        "{%0,%1,%2,%3}, {%4,%5,%6,%7}, {%8,%9}, {%0,%1,%2,%3};"
        : "+f"(d[0]), "+f"(d[1]), "+f"(d[2]), "+f"(d[3])
        : "r"(a[0]), "r"(a[1]), "r"(a[2]), "r"(a[3]), "r"(b[0]), "r"(b[1]));
}

/* smem tiles (halves): A[128][24] (48B rows), B[16][136] (272B rows) */
#define A_LDA 24
#define B_LDB 136
#define A_HALVES (128 * A_LDA)            /* 3072 */
#define B_HALVES (16 * B_LDB)             /* 2176 */
#define G1_STAGE_H (A_HALVES + 2 * B_HALVES)
#define G1_SMEM (512 + 2 * G1_STAGE_H * 2)
#define G2_STAGE_H (A_HALVES + B_HALVES)
#define G2_SMEM (512 + 2 * G2_STAGE_H * 2)

/* ---------------- small kernels ---------------- */
__global__ void k_zero_counts() { if (threadIdx.x < NEXP) g_counts[threadIdx.x] = 0; }

__global__ void k_zero_out(float4* __restrict__ out) {
    size_t i = (size_t)blockIdx.x * blockDim.x + threadIdx.x;
    if (i < (size_t)TTOK * HDIM / 4) out[i] = make_float4(0.f, 0.f, 0.f, 0.f);
}

__global__ void __launch_bounds__(256) k_router(const float* __restrict__ x,
                                                const float* __restrict__ gw) {
    __shared__ float As[16][64];
    __shared__ float Bs[16][64];
    const int t = threadIdx.x;
    const int m0 = blockIdx.x * 64;
    const int tx = t & 15, ty = t >> 4;
    const int mload = t >> 2;
    const int kq = (t & 3) * 4;
    float acc[4][4] = {};
    for (int k0 = 0; k0 < HDIM; k0 += 16) {
        float4 av = LD4(x + (size_t)(m0 + mload) * HDIM + k0 + kq);
        float4 bv = LD4(gw + (size_t)mload * HDIM + k0 + kq);
        __syncthreads();
        As[kq + 0][mload] = av.x; As[kq + 1][mload] = av.y;
        As[kq + 2][mload] = av.z; As[kq + 3][mload] = av.w;
        Bs[kq + 0][mload] = bv.x; Bs[kq + 1][mload] = bv.y;
        Bs[kq + 2][mload] = bv.z; Bs[kq + 3][mload] = bv.w;
        __syncthreads();
#pragma unroll
        for (int k = 0; k < 16; k++) {
            float4 a = LD4(&As[k][ty * 4]);
            float4 b = LD4(&Bs[k][tx * 4]);
            float ax[4] = {a.x, a.y, a.z, a.w};
            float bx[4] = {b.x, b.y, b.z, b.w};
#pragma unroll
            for (int i = 0; i < 4; i++)
#pragma unroll
                for (int j = 0; j < 4; j++)
                    acc[i][j] = fmaf(ax[i], bx[j], acc[i][j]);
        }
    }
#pragma unroll
    for (int i = 0; i < 4; i++)
#pragma unroll
        for (int j = 0; j < 4; j++)
            g_logits[(size_t)(m0 + ty * 4 + i) * NEXP + tx * 4 + j] = acc[i][j];
}

__global__ void k_topk() {
    int t = blockIdx.x * blockDim.x + threadIdx.x;
    if (t >= TTOK) return;
    float l[NEXP];
    for (int e = 0; e < NEXP; e++) l[e] = g_logits[(size_t)t * NEXP + e];
    float vals[TOPK]; int ids[TOPK];
    for (int k = 0; k < TOPK; k++) {
        float best = -3.4e38f; int bi = 0;
        for (int e = 0; e < NEXP; e++)
            if (l[e] > best) { best = l[e]; bi = e; }
        vals[k] = best; ids[k] = bi; l[bi] = -3.4e38f;
    }
    float m = vals[0], s = 0.f, wv[TOPK];
    for (int k = 0; k < TOPK; k++) { wv[k] = expf(vals[k] - m); s += wv[k]; }
    float inv = 1.f / s;
    for (int k = 0; k < TOPK; k++) {
        g_topkw[t * TOPK + k] = wv[k] * inv;
        int e = ids[k];
        int pos = atomicAdd(&g_counts[e], 1);
        g_bucket[e * CAP + pos] = t * TOPK + k;
    }
}

__global__ void k_scan() {
    int s = 0;
    for (int e = 0; e < NEXP; e++) { g_offsets[e] = s; s += g_counts[e]; }
}

/* ================= stage 4: fused gate/up fp16 HMMA GEMM + SiLU ================= */
__global__ void __launch_bounds__(256)
k_gemm1(const float* __restrict__ x, const float* __restrict__ wgt, const float* __restrict__ wup) {
    extern __shared__ char smraw[];
    const int e = blockIdx.z;
    const int rows = g_counts[e];
    const int m0 = blockIdx.y * 128;
    if (m0 >= rows) return;
    const int n0 = blockIdx.x * 128;
    const int t = threadIdx.x, w = t >> 5, lane = t & 31;
    const int gid = lane >> 2, tig = lane & 3;
    const int wm = w >> 2, wn = w & 3;

    int* toks = (int*)smraw;
    __half* buf = (__half*)(smraw + 512);
    if (t < 128) {
        int r = m0 + t;
        toks[t] = (r < rows) ? (g_bucket[e * CAP + r] >> 3) : -1;
    }
    __syncthreads();

    const float* bg = wgt + (size_t)e * HDIM * IDIM;
    const float* bu = wup + (size_t)e * HDIM * IDIM;

    const int am = t >> 1, akh = (t & 1) * 8;
    const int tokA = toks[am];
    const bool aval = (tokA >= 0);
    const float* aptr = x + (size_t)(aval ? tokA : 0) * HDIM;
    const int bq = t & 127, bk = bq >> 3, bn = (bq & 7) * 16;
    const float* bsrc = (t < 128) ? bg : bu;
    const int bhoff = A_HALVES + ((t < 128) ? 0 : B_HALVES);

    float4 pa0, pa1, pb0, pb1, pb2, pb3;
    if (aval) { pa0 = LD4(aptr + akh); pa1 = LD4(aptr + akh + 4); }
    else { pa0 = make_float4(0, 0, 0, 0); pa1 = pa0; }
    { const float* s = bsrc + (size_t)bk * IDIM + n0 + bn;
      pb0 = LD4(s); pb1 = LD4(s + 4); pb2 = LD4(s + 8); pb3 = LD4(s + 12); }

    float cg[4][4][4] = {}, cu[4][4][4] = {};

    /* per-lane ldmatrix row/col offsets */
    const int aRow = wm * 64 + (lane & 15);
    const int aK   = (lane >> 4) * 8;
    const int bK   = lane & 15;

    const int KT = HDIM / 16;
    for (int kt = 0; kt < KT; kt++) {
        __half* st = buf + (kt & 1) * G1_STAGE_H;
        __syncthreads();
        *reinterpret_cast<uint4*>(st + am * A_LDA + akh) = pack8(pa0, pa1);
        { __half* p = st + bhoff + bk * B_LDB + bn;
          *reinterpret_cast<uint4*>(p)     = pack8(pb0, pb1);
          *reinterpret_cast<uint4*>(p + 8) = pack8(pb2, pb3); }
        __syncthreads();
        if (kt + 1 < KT) {
            const int kb = (kt + 1) * 16;
            if (aval) { pa0 = LD4(aptr + kb + akh); pa1 = LD4(aptr + kb + akh + 4); }
            const float* s = bsrc + (size_t)(kb + bk) * IDIM + n0 + bn;
            pb0 = LD4(s); pb1 = LD4(s + 4); pb2 = LD4(s + 8); pb3 = LD4(s + 12);
        }
        const uint32_t aAddr  = smem_u32(st + aRow * A_LDA + aK);
        const uint32_t bgAddr = smem_u32(st + A_HALVES + bK * B_LDB + wn * 32);
        const uint32_t buAddr = bgAddr + B_HALVES * 2;
        uint32_t af[4][4];
#pragma unroll
        for (int mt = 0; mt < 4; mt++) ldsm4(af[mt], aAddr + mt * 16 * A_LDA * 2);
#pragma unroll
        for (int nt = 0; nt < 4; nt++) {
            uint32_t b[2];
            ldsm2t(b, bgAddr + nt * 16);
#pragma unroll
            for (int mt = 0; mt < 4; mt++) mma16(cg[mt][nt], af[mt], b);
            ldsm2t(b, buAddr + nt * 16);
#pragma unroll
            for (int mt = 0; mt < 4; mt++) mma16(cu[mt][nt], af[mt], b);
        }
    }
    /* fused SiLU epilogue -> g_act (fp16) */
    __half* gact = (__half*)g_act4;
    const int off = g_offsets[e];
#pragma unroll
    for (int mt = 0; mt < 4; mt++) {
#pragma unroll
        for (int h = 0; h < 2; h++) {
            const int row = m0 + wm * 64 + mt * 16 + gid + h * 8;
            if (row < rows) {
                __half* dst = gact + (size_t)(off + row) * IDIM + n0 + wn * 32;
#pragma unroll
                for (int nt = 0; nt < 4; nt++) {
                    float g0 = cg[mt][nt][h * 2 + 0], g1 = cg[mt][nt][h * 2 + 1];
                    float u0 = cu[mt][nt][h * 2 + 0], u1 = cu[mt][nt][h * 2 + 1];
                    float o0 = g0 / (1.f + expf(-g0)) * u0;
                    float o1 = g1 / (1.f + expf(-g1)) * u1;
                    *reinterpret_cast<uint32_t*>(dst + nt * 8 + 2 * tig) = pk2(o0, o1);
                }
            }
        }
    }
}

/* ================= stage 5: down-proj fp16 HMMA GEMM + fused weighted combine ===== */
__global__ void __launch_bounds__(256)
k_gemm2(const float* __restrict__ wdn, float* __restrict__ out) {
    extern __shared__ char smraw[];
    const int e = blockIdx.z;
    const int rows = g_counts[e];
    const int m0 = blockIdx.y * 128;
    if (m0 >= rows) return;
    const int n0 = blockIdx.x * 128;
    const int t = threadIdx.x, w = t >> 5, lane = t & 31;
    const int gid = lane >> 2, tig = lane & 3;
    const int wm = w >> 2, wn = w & 3;
    const int off = g_offsets[e];

    int* prs = (int*)smraw;
    __half* buf = (__half*)(smraw + 512);
    if (t < 128) {
        int r = m0 + t;
        prs[t] = (r < rows) ? g_bucket[e * CAP + r] : -1;
    }
    __syncthreads();

    const float* bsrc = wdn + (size_t)e * IDIM * HDIM;
    const __half* gact = (const __half*)g_act4;

    const int am = t >> 1, akh = (t & 1) * 8;
    const bool aval = (m0 + am < rows);
    const __half* aptr = gact + (size_t)(off + m0 + (aval ? am : 0)) * IDIM;
    const int bk = t >> 4, bn = (t & 15) * 8;

    uint4 pa; float4 pb0, pb1;
    if (aval) pa = *reinterpret_cast<const uint4*>(aptr + akh);
    else pa = make_uint4(0, 0, 0, 0);
    { const float* s = bsrc + (size_t)bk * HDIM + n0 + bn;
      pb0 = LD4(s); pb1 = LD4(s + 4); }

    float cd[4][4][4] = {};

    const int aRow = wm * 64 + (lane & 15);
    const int aK   = (lane >> 4) * 8;
    const int bK   = lane & 15;

    const int KT = IDIM / 16;
    for (int kt = 0; kt < KT; kt++) {
        __half* st = buf + (kt & 1) * G2_STAGE_H;
        __syncthreads();
        *reinterpret_cast<uint4*>(st + am * A_LDA + akh) = pa;
        *reinterpret_cast<uint4*>(st + A_HALVES + bk * B_LDB + bn) = pack8(pb0, pb1);
        __syncthreads();
        if (kt + 1 < KT) {
            const int kb = (kt + 1) * 16;
            if (aval) pa = *reinterpret_cast<const uint4*>(aptr + kb + akh);
            const float* s = bsrc + (size_t)(kb + bk) * HDIM + n0 + bn;
            pb0 = LD4(s); pb1 = LD4(s + 4);
        }
        const uint32_t aAddr = smem_u32(st + aRow * A_LDA + aK);
        const uint32_t bAddr = smem_u32(st + A_HALVES + bK * B_LDB + wn * 32);
        uint32_t af[4][4];
#pragma unroll
        for (int mt = 0; mt < 4; mt++) ldsm4(af[mt], aAddr + mt * 16 * A_LDA * 2);
#pragma unroll
        for (int nt = 0; nt < 4; nt++) {
            uint32_t b[2];
            ldsm2t(b, bAddr + nt * 16);
#pragma unroll
            for (int mt = 0; mt < 4; mt++) mma16(cd[mt][nt], af[mt], b);
        }
    }
    /* fused combine: scale by routing weight, atomically accumulate into out */
#pragma unroll
    for (int mt = 0; mt < 4; mt++) {
#pragma unroll
        for (int h = 0; h < 2; h++) {
            const int lr = wm * 64 + mt * 16 + gid + h * 8;
            const int p = prs[lr];
            if (p >= 0) {
                const float wv = g_topkw[p];
                const int tok = p >> 3;
                float* dst = out + (size_t)tok * HDIM + n0 + wn * 32;
#pragma unroll
                for (int nt = 0; nt < 4; nt++) {
                    atomicAdd(dst + nt * 8 + 2 * tig,     wv * cd[mt][nt][h * 2 + 0]);
                    atomicAdd(dst + nt * 8 + 2 * tig + 1, wv * cd[mt][nt][h * 2 + 1]);
                }
            }
        }
    }
}

/* ---------------- launch ---------------- */
extern "C" void kernel_launch(void* const* d_in, const int* /*in_sizes*/, int /*n_in*/,
                              void* d_out, int /*out_size*/) {
    const float* x   = (const float*)d_in[0];
    const float* gw  = (const float*)d_in[1];
    const float* wgt = (const float*)d_in[2];
    const float* wup = (const float*)d_in[3];
    const float* wdn = (const float*)d_in[4];
    float* out = (float*)d_out;

    cudaFuncSetAttribute(k_gemm1, cudaFuncAttributeMaxDynamicSharedMemorySize, G1_SMEM);
    cudaFuncSetAttribute(k_gemm2, cudaFuncAttributeMaxDynamicSharedMemorySize, G2_SMEM);

    k_zero_out<<<TTOK * HDIM / 4 / 256, 256>>>((float4*)out);
    k_zero_counts<<<1, 64>>>();
    k_router<<<TTOK / 64, 256>>>(x, gw);
    k_topk<<<TTOK / 256, 256>>>();
    k_scan<<<1, 1>>>();
    k_gemm1<<<dim3(IDIM / 128, CAP / 128, NEXP), 256, G1_SMEM>>>(x, wgt, wup);
    k_gemm2<<<dim3(HDIM / 128, CAP / 128, NEXP), 256, G2_SMEM>>>(wdn, out);
}